// round 2
// baseline (speedup 1.0000x reference)
#include <cuda_runtime.h>
#include <cstdint>
#include <math.h>

// Problem constants
#define BB   8
#define SS   8192
#define HH   768
#define MM   (BB*SS)      // 65536 GEMM rows
#define KK   768          // GEMM K
#define NT   12           // number of 64-wide a/g column tiles (768/64)
#define LAM  0.1f

#define BKT  32           // GEMM k-tile
#define KITR (KK/BKT)     // 24
#define STAGE_F (128*32)  // floats per smem stage per matrix (4096)
#define SMEM_GEMM_BYTES (2*3*STAGE_F*4)   // 98304

// ---------------- device scratch (allocation-free rule: __device__ globals) ----
__device__ float g_v[(size_t)MM*HH];        // silu(x*D + conv), tf32-rounded (201MB)
__device__ float g_w[NT*128*KK];            // W permuted into [nT][128 rows: 64 a | 64 g][K], tf32-rounded
__device__ float g_tapv[HH*SS];             // compacted soft-thresholded kernel taps (value)
__device__ int   g_tapi[HH*SS];             // compacted taps (delay index)
__device__ int   g_nnz[HH];                 // taps per channel

// ---------------- helpers ----------------
__device__ __forceinline__ void cp16(float* s, const float* g) {
    uint32_t sa = (uint32_t)__cvta_generic_to_shared(s);
    asm volatile("cp.async.cg.shared.global [%0], [%1], 16;" :: "r"(sa), "l"(g));
}
__device__ __forceinline__ void cp_commit() { asm volatile("cp.async.commit_group;"); }

__device__ __forceinline__ uint32_t f2tf32(float f) {
    uint32_t o;
    asm("cvt.rna.tf32.f32 %0, %1;" : "=r"(o) : "r"(__float_as_uint(f)));
    return o;
}

__device__ __forceinline__ void mma_tf32(float c[4], const uint32_t a[4], const uint32_t b[2]) {
    asm("mma.sync.aligned.m16n8k8.row.col.f32.tf32.tf32.f32 "
        "{%0,%1,%2,%3}, {%4,%5,%6,%7}, {%8,%9}, {%0,%1,%2,%3};"
        : "+f"(c[0]), "+f"(c[1]), "+f"(c[2]), "+f"(c[3])
        : "r"(a[0]), "r"(a[1]), "r"(a[2]), "r"(a[3]), "r"(b[0]), "r"(b[1]));
}

// ---------------- kernel 1: soft-threshold + compact nonzero taps per channel ----
__global__ void k_taps(const float* __restrict__ ker) {
    __shared__ int cnt;
    const int h = blockIdx.x;
    if (threadIdx.x == 0) cnt = 0;
    __syncthreads();
    const float* kr = ker + (size_t)h*SS;
    for (int t = threadIdx.x; t < SS; t += blockDim.x) {
        float kv = kr[t];
        float av = fabsf(kv) - LAM;
        if (av > 0.0f) {
            int p = atomicAdd(&cnt, 1);
            g_tapv[(size_t)h*SS + p] = copysignf(av, kv);
            g_tapi[(size_t)h*SS + p] = t;
        }
    }
    __syncthreads();
    if (threadIdx.x == 0) g_nnz[h] = cnt;
}

// ---------------- kernel 2: permute+round W into a/g-paired tiles -------------
// g_w[nT][r][k]: r<64 -> W[nT*64 + r]  (the 'a' rows, output cols h = nT*64+r)
//               r>=64 -> W[768 + nT*64 + (r-64)]  (the matching 'g' rows)
__global__ void k_wprep(const float* __restrict__ W) {
    int idx = blockIdx.x * blockDim.x + threadIdx.x;
    if (idx >= NT*128*KK) return;
    int k  = idx % KK;
    int r  = (idx / KK) % 128;
    int nT = idx / (128*KK);
    int srcRow = (r < 64) ? (nT*64 + r) : (768 + nT*64 + (r - 64));
    g_w[idx] = __uint_as_float(f2tf32(W[(size_t)srcRow*KK + k]));
}

// ---------------- kernel 3: v = silu(x*D + sparse_conv), tf32-rounded ---------
__global__ void k_v(const float* __restrict__ x, const float* __restrict__ D) {
    int i4 = blockIdx.x * blockDim.x + threadIdx.x;   // float4 index over M*H/4
    int m  = i4 / (HH/4);
    int h0 = (i4 - m*(HH/4)) * 4;
    const float4 xv = *(const float4*)(x + (size_t)m*HH + h0);
    const float4 dv = *(const float4*)(D + h0);
    const int4  nn = *(const int4*)(g_nnz + h0);
    float y[4] = { xv.x*dv.x, xv.y*dv.y, xv.z*dv.z, xv.w*dv.w };
    if (nn.x | nn.y | nn.z | nn.w) {     // sparse causal conv (general correctness path)
        const int s = m & (SS-1);
        const int nnc[4] = { nn.x, nn.y, nn.z, nn.w };
        for (int c = 0; c < 4; c++) {
            const int h = h0 + c;
            for (int j = 0; j < nnc[c]; j++) {
                int t = g_tapi[(size_t)h*SS + j];
                if (t <= s) y[c] += g_tapv[(size_t)h*SS + j] * x[(size_t)(m - t)*HH + h];
            }
        }
    }
    float4 o;
    float* op = &o.x;
    #pragma unroll
    for (int c = 0; c < 4; c++) {
        float z  = y[c];
        float sv = z / (1.0f + expf(-z));            // silu
        op[c] = __uint_as_float(f2tf32(sv));
    }
    *(float4*)(g_v + (size_t)m*HH + h0) = o;
}

// ---------------- kernel 4: tf32 GEMM + bias + GLU + residual -----------------
// C[128 x 128] = v_tile @ g_w_tile^T ; local cols [0,64)=a, [64,128)=g (same h)
__global__ void __launch_bounds__(256, 1)
k_gemm(const float* __restrict__ x, const float* __restrict__ bias,
       float* __restrict__ out) {
    extern __shared__ float sm[];
    float* As = sm;                      // [3][128][32], xor-swizzled
    float* Bs = sm + 3*STAGE_F;

    const int tid  = threadIdx.x;
    const int warp = tid >> 5, lane = tid & 31;
    const int g    = lane >> 2, t = lane & 3;
    const int wm   = (warp & 3) * 32;    // warp M offset (4 warps in M)
    const int wn   = (warp >> 2) * 64;   // warp N offset (2 warps in N)
    const int nT   = blockIdx.x;
    const int m0   = blockIdx.y * 128;

    const float* gA = g_v + (size_t)m0*KK;
    const float* gB = g_w + (size_t)nT*128*KK;

    const int lr = tid >> 3;             // load row 0..31 (x4 iters -> 128 rows)
    const int lc = (tid & 7) * 4;        // load col (floats)

    float c[2][8][4];
    #pragma unroll
    for (int i = 0; i < 2; i++)
        #pragma unroll
        for (int j = 0; j < 8; j++)
            #pragma unroll
            for (int q = 0; q < 4; q++) c[i][j][q] = 0.0f;

    // ---- async stage loader (xor swizzle: elem (r,k) at r*32 + ((k>>2)^(r&7))*4 + (k&3))
    #define ISSUE_STAGE(stg, kt_)                                              \
    {                                                                          \
        const int k0_ = (kt_) * BKT;                                           \
        _Pragma("unroll")                                                      \
        for (int i_ = 0; i_ < 4; i_++) {                                       \
            int r_  = lr + i_*32;                                              \
            int sw_ = (((lc >> 2) ^ (r_ & 7)) << 2);                           \
            cp16(As + (stg)*STAGE_F + r_*32 + sw_, gA + (size_t)r_*KK + k0_ + lc); \
            cp16(Bs + (stg)*STAGE_F + r_*32 + sw_, gB + (size_t)r_*KK + k0_ + lc); \
        }                                                                      \
    }

    ISSUE_STAGE(0, 0); cp_commit();
    ISSUE_STAGE(1, 1); cp_commit();

    for (int kt = 0; kt < KITR; kt++) {
        asm volatile("cp.async.wait_group 1;");
        __syncthreads();
        if (kt + 2 < KITR) { ISSUE_STAGE((kt+2)%3, kt+2); }
        cp_commit();

        const float* A_ = As + (kt%3)*STAGE_F;
        const float* B_ = Bs + (kt%3)*STAGE_F;

        #pragma unroll
        for (int ks = 0; ks < 4; ks++) {
            const int sw0 = (((2*ks  ) ^ g) << 2) + t;   // swizzled col for k = 8ks + t
            const int sw1 = (((2*ks+1) ^ g) << 2) + t;   // swizzled col for k = 8ks + t + 4
            uint32_t af[2][4], bf[8][2];
            #pragma unroll
            for (int mt = 0; mt < 2; mt++) {
                int r0 = wm + mt*16 + g;
                af[mt][0] = __float_as_uint(A_[ r0    *32 + sw0]);
                af[mt][1] = __float_as_uint(A_[(r0+8)*32 + sw0]);
                af[mt][2] = __float_as_uint(A_[ r0    *32 + sw1]);
                af[mt][3] = __float_as_uint(A_[(r0+8)*32 + sw1]);
            }
            #pragma unroll
            for (int nt = 0; nt < 8; nt++) {
                int nb = wn + nt*8 + g;
                bf[nt][0] = __float_as_uint(B_[nb*32 + sw0]);
                bf[nt][1] = __float_as_uint(B_[nb*32 + sw1]);
            }
            #pragma unroll
            for (int mt = 0; mt < 2; mt++)
                #pragma unroll
                for (int nt = 0; nt < 8; nt++)
                    mma_tf32(c[mt][nt], af[mt], bf[nt]);
        }
    }
    asm volatile("cp.async.wait_group 0;");
    __syncthreads();

    // ---- stage C through smem so (a,g) pairs are visible to one thread ----
    float* Cs = sm;                       // [128][132]
    #pragma unroll
    for (int mt = 0; mt < 2; mt++)
        #pragma unroll
        for (int nt = 0; nt < 8; nt++) {
            int r = wm + mt*16 + g, cc = wn + nt*8 + 2*t;
            Cs[ r   *132 + cc    ] = c[mt][nt][0];
            Cs[ r   *132 + cc + 1] = c[mt][nt][1];
            Cs[(r+8)*132 + cc    ] = c[mt][nt][2];
            Cs[(r+8)*132 + cc + 1] = c[mt][nt][3];
        }
    __syncthreads();

    // ---- bias + GLU + residual, write final output ----
    #pragma unroll
    for (int i = 0; i < 32; i++) {
        int idx = i*256 + tid;            // 128*64 outputs
        int r = idx >> 6, j = idx & 63;
        int h = nT*64 + j;
        float a  = Cs[r*132 + j     ] + bias[h];
        float gg = Cs[r*132 + j + 64] + bias[h + 768];
        float sg = 1.0f / (1.0f + expf(-gg));
        size_t off = (size_t)(m0 + r)*HH + h;
        out[off] = a * sg + x[off];
    }
    #undef ISSUE_STAGE
}

// ---------------- launch ----------------
extern "C" void kernel_launch(void* const* d_in, const int* in_sizes, int n_in,
                              void* d_out, int out_size) {
    const float* x    = (const float*)d_in[0];   // (8, 8192, 768)
    const float* ker  = (const float*)d_in[1];   // (1, 768, 8192)
    const float* D    = (const float*)d_in[2];   // (1, 768)
    const float* W    = (const float*)d_in[3];   // (1536, 768)
    const float* bias = (const float*)d_in[4];   // (1536,)
    float* out = (float*)d_out;                  // (8, 8192, 768)

    k_taps<<<HH, 256>>>(ker);
    k_wprep<<<(NT*128*KK + 255)/256, 256>>>(W);
    k_v<<<(MM*(HH/4))/256, 256>>>(x, D);

    (void)cudaFuncSetAttribute(k_gemm, cudaFuncAttributeMaxDynamicSharedMemorySize,
                               SMEM_GEMM_BYTES);
    dim3 grid(NT, MM/128);
    k_gemm<<<grid, 256, SMEM_GEMM_BYTES>>>(x, bias, out);
}

// round 3
// speedup vs baseline: 1.6337x; 1.6337x over previous
#include <cuda_runtime.h>
#include <cstdint>
#include <math.h>

// Problem constants
#define BB   8
#define SS   8192
#define HH   768
#define MM   (BB*SS)      // 65536 GEMM rows
#define KK   768          // GEMM K
#define NT   12           // number of 64-wide a/g column tiles (768/64)
#define LAM  0.1f

#define BKT  32           // GEMM k-tile
#define KITR (KK/BKT)     // 24
#define STAGE_F (128*32)  // floats per smem stage per matrix (4096)
#define SMEM_GEMM_BYTES (2*3*STAGE_F*4)   // 98304 (2 CTAs/SM -> 192KB of 228KB)

// ---------------- device scratch (allocation-free rule: __device__ globals) ----
__device__ float g_v[(size_t)MM*HH];        // silu(x*D + conv), tf32-rounded (201MB)
__device__ float g_w[NT*128*KK];            // W permuted into [nT][128 rows: 64 a | 64 g][K], tf32-rounded
__device__ float g_tapv[HH*SS];             // compacted soft-thresholded kernel taps (value)
__device__ int   g_tapi[HH*SS];             // compacted taps (delay index)
__device__ int   g_nnz[HH];                 // taps per channel

// ---------------- helpers ----------------
__device__ __forceinline__ void cp16(float* s, const float* g) {
    uint32_t sa = (uint32_t)__cvta_generic_to_shared(s);
    asm volatile("cp.async.cg.shared.global [%0], [%1], 16;" :: "r"(sa), "l"(g));
}
__device__ __forceinline__ void cp_commit() { asm volatile("cp.async.commit_group;"); }

__device__ __forceinline__ uint32_t f2tf32(float f) {
    uint32_t o;
    asm("cvt.rna.tf32.f32 %0, %1;" : "=r"(o) : "r"(__float_as_uint(f)));
    return o;
}

__device__ __forceinline__ void mma_tf32(float c[4], const uint32_t a[4], const uint32_t b[2]) {
    asm("mma.sync.aligned.m16n8k8.row.col.f32.tf32.tf32.f32 "
        "{%0,%1,%2,%3}, {%4,%5,%6,%7}, {%8,%9}, {%0,%1,%2,%3};"
        : "+f"(c[0]), "+f"(c[1]), "+f"(c[2]), "+f"(c[3])
        : "r"(a[0]), "r"(a[1]), "r"(a[2]), "r"(a[3]), "r"(b[0]), "r"(b[1]));
}

// ---------------- kernel 1: soft-threshold + compact nonzero taps per channel ----
__global__ void k_taps(const float* __restrict__ ker) {
    __shared__ int cnt;
    const int h = blockIdx.x;
    if (threadIdx.x == 0) cnt = 0;
    __syncthreads();
    const float* kr = ker + (size_t)h*SS;
    for (int t = threadIdx.x; t < SS; t += blockDim.x) {
        float kv = kr[t];
        float av = fabsf(kv) - LAM;
        if (av > 0.0f) {
            int p = atomicAdd(&cnt, 1);
            g_tapv[(size_t)h*SS + p] = copysignf(av, kv);
            g_tapi[(size_t)h*SS + p] = t;
        }
    }
    __syncthreads();
    if (threadIdx.x == 0) g_nnz[h] = cnt;
}

// ---------------- kernel 2: permute+round W into a/g-paired tiles -------------
__global__ void k_wprep(const float* __restrict__ W) {
    int idx = blockIdx.x * blockDim.x + threadIdx.x;
    if (idx >= NT*128*KK) return;
    int k  = idx % KK;
    int r  = (idx / KK) % 128;
    int nT = idx / (128*KK);
    int srcRow = (r < 64) ? (nT*64 + r) : (768 + nT*64 + (r - 64));
    g_w[idx] = __uint_as_float(f2tf32(W[(size_t)srcRow*KK + k]));
}

// ---------------- kernel 3: v = silu(x*D + sparse_conv), tf32-rounded ---------
__global__ void k_v(const float* __restrict__ x, const float* __restrict__ D) {
    int i4 = blockIdx.x * blockDim.x + threadIdx.x;   // float4 index over M*H/4
    int m  = i4 / (HH/4);
    int h0 = (i4 - m*(HH/4)) * 4;
    const float4 xv = *(const float4*)(x + (size_t)m*HH + h0);
    const float4 dv = *(const float4*)(D + h0);
    const int4  nn = *(const int4*)(g_nnz + h0);
    float y[4] = { xv.x*dv.x, xv.y*dv.y, xv.z*dv.z, xv.w*dv.w };
    if (nn.x | nn.y | nn.z | nn.w) {     // sparse causal conv (general correctness path)
        const int s = m & (SS-1);
        const int nnc[4] = { nn.x, nn.y, nn.z, nn.w };
        for (int c = 0; c < 4; c++) {
            const int h = h0 + c;
            for (int j = 0; j < nnc[c]; j++) {
                int t = g_tapi[(size_t)h*SS + j];
                if (t <= s) y[c] += g_tapv[(size_t)h*SS + j] * x[(size_t)(m - t)*HH + h];
            }
        }
    }
    float4 o;
    float* op = &o.x;
    #pragma unroll
    for (int c = 0; c < 4; c++) {
        float z  = y[c];
        float sv = z / (1.0f + expf(-z));            // silu
        op[c] = __uint_as_float(f2tf32(sv));
    }
    *(float4*)(g_v + (size_t)m*HH + h0) = o;
}

// ---------------- kernel 4: tf32 GEMM + bias + GLU + residual -----------------
// C[128 x 128] = v_tile @ g_w_tile^T ; local cols [0,64)=a, [64,128)=g (same h)
__global__ void __launch_bounds__(256, 2)
k_gemm(const float* __restrict__ x, const float* __restrict__ bias,
       float* __restrict__ out) {
    extern __shared__ float sm[];
    float* As = sm;                      // [3][128][32], xor-swizzled
    float* Bs = sm + 3*STAGE_F;

    const int tid  = threadIdx.x;
    const int warp = tid >> 5, lane = tid & 31;
    const int g    = lane >> 2, t = lane & 3;
    const int wm   = (warp & 3) * 32;    // warp M offset (4 warps in M)
    const int wn   = (warp >> 2) * 64;   // warp N offset (2 warps in N)
    const int nT   = blockIdx.x;
    const int m0   = blockIdx.y * 128;

    const float* gA = g_v + (size_t)m0*KK;
    const float* gB = g_w + (size_t)nT*128*KK;

    const int lr = tid >> 3;             // load row 0..31 (x4 iters -> 128 rows)
    const int lc = (tid & 7) * 4;        // load col (floats)

    float c[2][8][4];
    #pragma unroll
    for (int i = 0; i < 2; i++)
        #pragma unroll
        for (int j = 0; j < 8; j++)
            #pragma unroll
            for (int q = 0; q < 4; q++) c[i][j][q] = 0.0f;

    // ---- async stage loader (xor swizzle: elem (r,k) at r*32 + ((k>>2)^(r&7))*4 + (k&3))
    #define ISSUE_STAGE(stg, kt_)                                              \
    {                                                                          \
        const int k0_ = (kt_) * BKT;                                           \
        _Pragma("unroll")                                                      \
        for (int i_ = 0; i_ < 4; i_++) {                                       \
            int r_  = lr + i_*32;                                              \
            int sw_ = (((lc >> 2) ^ (r_ & 7)) << 2);                           \
            cp16(As + (stg)*STAGE_F + r_*32 + sw_, gA + (size_t)r_*KK + k0_ + lc); \
            cp16(Bs + (stg)*STAGE_F + r_*32 + sw_, gB + (size_t)r_*KK + k0_ + lc); \
        }                                                                      \
    }

    ISSUE_STAGE(0, 0); cp_commit();
    ISSUE_STAGE(1, 1); cp_commit();

    for (int kt = 0; kt < KITR; kt++) {
        asm volatile("cp.async.wait_group 1;");
        __syncthreads();
        if (kt + 2 < KITR) { ISSUE_STAGE((kt+2)%3, kt+2); }
        cp_commit();

        const float* A_ = As + (kt%3)*STAGE_F;
        const float* B_ = Bs + (kt%3)*STAGE_F;

        #pragma unroll
        for (int ks = 0; ks < 4; ks++) {
            const int sw0 = (((2*ks  ) ^ g) << 2) + t;   // swizzled col for k = 8ks + t
            const int sw1 = (((2*ks+1) ^ g) << 2) + t;   // swizzled col for k = 8ks + t + 4
            uint32_t af[2][4], bf[8][2];
            #pragma unroll
            for (int mt = 0; mt < 2; mt++) {
                int r0 = wm + mt*16 + g;
                af[mt][0] = __float_as_uint(A_[ r0    *32 + sw0]);
                af[mt][1] = __float_as_uint(A_[(r0+8)*32 + sw0]);
                af[mt][2] = __float_as_uint(A_[ r0    *32 + sw1]);
                af[mt][3] = __float_as_uint(A_[(r0+8)*32 + sw1]);
            }
            #pragma unroll
            for (int nt = 0; nt < 8; nt++) {
                int nb = wn + nt*8 + g;
                bf[nt][0] = __float_as_uint(B_[nb*32 + sw0]);
                bf[nt][1] = __float_as_uint(B_[nb*32 + sw1]);
            }
            #pragma unroll
            for (int mt = 0; mt < 2; mt++)
                #pragma unroll
                for (int nt = 0; nt < 8; nt++)
                    mma_tf32(c[mt][nt], af[mt], bf[nt]);
        }
    }
    asm volatile("cp.async.wait_group 0;");
    __syncthreads();

    // ---- stage C through smem so (a,g) pairs are visible to one thread ----
    float* Cs = sm;                       // [128][132]
    #pragma unroll
    for (int mt = 0; mt < 2; mt++)
        #pragma unroll
        for (int nt = 0; nt < 8; nt++) {
            int r = wm + mt*16 + g, cc = wn + nt*8 + 2*t;
            Cs[ r   *132 + cc    ] = c[mt][nt][0];
            Cs[ r   *132 + cc + 1] = c[mt][nt][1];
            Cs[(r+8)*132 + cc    ] = c[mt][nt][2];
            Cs[(r+8)*132 + cc + 1] = c[mt][nt][3];
        }
    __syncthreads();

    // ---- bias + GLU + residual, write final output ----
    #pragma unroll
    for (int i = 0; i < 32; i++) {
        int idx = i*256 + tid;            // 128*64 outputs
        int r = idx >> 6, j = idx & 63;
        int h = nT*64 + j;
        float a  = Cs[r*132 + j     ] + bias[h];
        float gg = Cs[r*132 + j + 64] + bias[h + 768];
        float sg = 1.0f / (1.0f + expf(-gg));
        size_t off = (size_t)(m0 + r)*HH + h;
        out[off] = a * sg + x[off];
    }
    #undef ISSUE_STAGE
}

// ---------------- launch ----------------
extern "C" void kernel_launch(void* const* d_in, const int* in_sizes, int n_in,
                              void* d_out, int out_size) {
    const float* x    = (const float*)d_in[0];   // (8, 8192, 768)
    const float* ker  = (const float*)d_in[1];   // (1, 768, 8192)
    const float* D    = (const float*)d_in[2];   // (1, 768)
    const float* W    = (const float*)d_in[3];   // (1536, 768)
    const float* bias = (const float*)d_in[4];   // (1536,)
    float* out = (float*)d_out;                  // (8, 8192, 768)

    k_taps<<<HH, 256>>>(ker);
    k_wprep<<<(NT*128*KK + 255)/256, 256>>>(W);
    k_v<<<(MM*(HH/4))/256, 256>>>(x, D);

    (void)cudaFuncSetAttribute(k_gemm, cudaFuncAttributeMaxDynamicSharedMemorySize,
                               SMEM_GEMM_BYTES);
    dim3 grid(NT, MM/128);
    k_gemm<<<grid, 256, SMEM_GEMM_BYTES>>>(x, bias, out);
}

// round 6
// speedup vs baseline: 1.7429x; 1.0669x over previous
#include <cuda_runtime.h>
#include <cstdint>
#include <math.h>

// Problem constants
#define BB   8
#define SS   8192
#define HH   768
#define MM   (BB*SS)      // 65536 GEMM rows
#define KK   768          // GEMM K
#define NT   12           // number of 64-wide a/g column tiles (768/64)
#define LAM  0.1f

#define BKT  32           // GEMM k-tile
#define KITR (KK/BKT)     // 24
#define STAGE_F (128*32)  // floats per smem stage per matrix (4096)
#define SMEM_GEMM_BYTES (2*3*STAGE_F*4)   // 98304 (2 CTAs/SM -> 192KB of 228KB)

// ---------------- device scratch (allocation-free rule: __device__ globals) ----
__device__ float g_v[(size_t)MM*HH];        // silu(x*D + conv), tf32-rounded (201MB)
__device__ float g_w[NT*128*KK];            // W permuted into [nT][128 rows: 64 a | 64 g][K]
__device__ float g_tapv[HH*SS];             // compacted soft-thresholded kernel taps (value)
__device__ int   g_tapi[HH*SS];             // compacted taps (delay index)
__device__ int   g_nnz[HH];                 // taps per channel

// ---------------- helpers ----------------
__device__ __forceinline__ void cp16(float* s, const float* g) {
    uint32_t sa = (uint32_t)__cvta_generic_to_shared(s);
    asm volatile("cp.async.cg.shared.global [%0], [%1], 16;" :: "r"(sa), "l"(g));
}
__device__ __forceinline__ void cp_commit() { asm volatile("cp.async.commit_group;"); }

__device__ __forceinline__ uint32_t f2tf32(float f) {
    uint32_t o;
    asm("cvt.rna.tf32.f32 %0, %1;" : "=r"(o) : "r"(__float_as_uint(f)));
    return o;
}

__device__ __forceinline__ void ldmx4(uint32_t& r0, uint32_t& r1, uint32_t& r2, uint32_t& r3,
                                      uint32_t addr) {
    asm volatile("ldmatrix.sync.aligned.m8n8.x4.shared.b16 {%0,%1,%2,%3}, [%4];"
                 : "=r"(r0), "=r"(r1), "=r"(r2), "=r"(r3) : "r"(addr));
}

__device__ __forceinline__ void mma_tf32(float c[4], const uint32_t a[4], const uint32_t b[2]) {
    asm("mma.sync.aligned.m16n8k8.row.col.f32.tf32.tf32.f32 "
        "{%0,%1,%2,%3}, {%4,%5,%6,%7}, {%8,%9}, {%0,%1,%2,%3};"
        : "+f"(c[0]), "+f"(c[1]), "+f"(c[2]), "+f"(c[3])
        : "r"(a[0]), "r"(a[1]), "r"(a[2]), "r"(a[3]), "r"(b[0]), "r"(b[1]));
}

// ---------------- kernel 1: soft-threshold + compact nonzero taps per channel ----
__global__ void k_taps(const float* __restrict__ ker) {
    __shared__ int cnt;
    const int h = blockIdx.x;
    if (threadIdx.x == 0) cnt = 0;
    __syncthreads();
    const float* kr = ker + (size_t)h*SS;
    for (int t = threadIdx.x; t < SS; t += blockDim.x) {
        float kv = kr[t];
        float av = fabsf(kv) - LAM;
        if (av > 0.0f) {
            int p = atomicAdd(&cnt, 1);
            g_tapv[(size_t)h*SS + p] = copysignf(av, kv);
            g_tapi[(size_t)h*SS + p] = t;
        }
    }
    __syncthreads();
    if (threadIdx.x == 0) g_nnz[h] = cnt;
}

// ---------------- kernel 2: permute+round W into a/g-paired tiles -------------
__global__ void k_wprep(const float* __restrict__ W) {
    int idx = blockIdx.x * blockDim.x + threadIdx.x;
    if (idx >= NT*128*KK) return;
    int k  = idx % KK;
    int r  = (idx / KK) % 128;
    int nT = idx / (128*KK);
    int srcRow = (r < 64) ? (nT*64 + r) : (768 + nT*64 + (r - 64));
    g_w[idx] = __uint_as_float(f2tf32(W[(size_t)srcRow*KK + k]));
}

// ---------------- kernel 3: v = silu(x*D + sparse_conv), tf32-rounded ---------
__global__ void k_v(const float* __restrict__ x, const float* __restrict__ D) {
    int i4 = blockIdx.x * blockDim.x + threadIdx.x;   // float4 index over M*H/4
    int m  = i4 / (HH/4);
    int h0 = (i4 - m*(HH/4)) * 4;
    const float4 xv = *(const float4*)(x + (size_t)m*HH + h0);
    const float4 dv = *(const float4*)(D + h0);
    const int4  nn = *(const int4*)(g_nnz + h0);
    float y[4] = { xv.x*dv.x, xv.y*dv.y, xv.z*dv.z, xv.w*dv.w };
    if (nn.x | nn.y | nn.z | nn.w) {     // sparse causal conv (general correctness path)
        const int s = m & (SS-1);
        const int nnc[4] = { nn.x, nn.y, nn.z, nn.w };
        for (int c = 0; c < 4; c++) {
            const int h = h0 + c;
            for (int j = 0; j < nnc[c]; j++) {
                int t = g_tapi[(size_t)h*SS + j];
                if (t <= s) y[c] += g_tapv[(size_t)h*SS + j] * x[(size_t)(m - t)*HH + h];
            }
        }
    }
    float4 o;
    float* op = &o.x;
    #pragma unroll
    for (int c = 0; c < 4; c++) {
        float z  = y[c];
        float sv = z / (1.0f + expf(-z));            // silu
        op[c] = __uint_as_float(f2tf32(sv));
    }
    *(float4*)(g_v + (size_t)m*HH + h0) = o;
}

// ---------------- kernel 4: tf32 GEMM + bias + GLU + residual -----------------
// C[128 x 128] = v_tile @ g_w_tile^T ; local cols [0,64)=a, [64,128)=g (same h)
// Fragment loads via ldmatrix.x4 (b16 view of tf32: 16B row = 4 elements).
__global__ void __launch_bounds__(256, 2)
k_gemm(const float* __restrict__ x, const float* __restrict__ bias,
       float* __restrict__ out) {
    extern __shared__ float sm[];
    float* As = sm;                      // [3][128][32], xor-swizzled (16B granules)
    float* Bs = sm + 3*STAGE_F;

    const int tid  = threadIdx.x;
    const int warp = tid >> 5, lane = tid & 31;
    const int g    = lane >> 2, t = lane & 3;
    const int wm   = (warp & 3) * 32;    // warp M offset (4 warps in M)
    const int wn   = (warp >> 2) * 64;   // warp N offset (2 warps in N)
    const int nT   = blockIdx.x;
    const int m0   = blockIdx.y * 128;

    const float* gA = g_v + (size_t)m0*KK;
    const float* gB = g_w + (size_t)nT*128*KK;

    const int lr = tid >> 3;             // load row 0..31 (x4 iters -> 128 rows)
    const int lc = (tid & 7) * 4;        // load col (floats)

    // ldmatrix lane decomposition: matrix j = lane>>3, row-in-matrix ri = lane&7
    const int jl = (lane >> 3) & 1;      // selects row-half (A) / k-half (B)
    const int jh = (lane >> 3) >> 1;     // selects k-half (A) / nt-in-pair (B)
    const int ri = lane & 7;
    const int ar0 = wm + jl*8 + ri;      // A row for mt=0 (mt=1 adds 16)
    int brow[4];                          // B rows for x4 groups p=0..3 (nt = 2p+jh)
    #pragma unroll
    for (int p = 0; p < 4; p++) brow[p] = wn + (2*p + jh)*8 + ri;

    const uint32_t smA = (uint32_t)__cvta_generic_to_shared(As);
    const uint32_t smB = (uint32_t)__cvta_generic_to_shared(Bs);

    float c[2][8][4];
    #pragma unroll
    for (int i = 0; i < 2; i++)
        #pragma unroll
        for (int j = 0; j < 8; j++)
            #pragma unroll
            for (int q = 0; q < 4; q++) c[i][j][q] = 0.0f;

    // ---- async stage loader (xor swizzle: elem (r,k) at r*32 + ((k>>2)^(r&7))*4 + (k&3))
    #define ISSUE_STAGE(stg, kt_)                                              \
    {                                                                          \
        const int k0_ = (kt_) * BKT;                                           \
        _Pragma("unroll")                                                      \
        for (int i_ = 0; i_ < 4; i_++) {                                       \
            int r_  = lr + i_*32;                                              \
            int sw_ = (((lc >> 2) ^ (r_ & 7)) << 2);                           \
            cp16(As + (stg)*STAGE_F + r_*32 + sw_, gA + (size_t)r_*KK + k0_ + lc); \
            cp16(Bs + (stg)*STAGE_F + r_*32 + sw_, gB + (size_t)r_*KK + k0_ + lc); \
        }                                                                      \
    }

    ISSUE_STAGE(0, 0); cp_commit();
    ISSUE_STAGE(1, 1); cp_commit();

    for (int kt = 0; kt < KITR; kt++) {
        asm volatile("cp.async.wait_group 1;");
        __syncthreads();
        if (kt + 2 < KITR) { ISSUE_STAGE((kt+2)%3, kt+2); }
        cp_commit();

        const uint32_t A_ = smA + (uint32_t)((kt%3)*STAGE_F)*4u;
        const uint32_t B_ = smB + (uint32_t)((kt%3)*STAGE_F)*4u;

        #pragma unroll
        for (int ks = 0; ks < 4; ks++) {
            uint32_t af[2][4], bf[8][2];
            // A frags: one ldmatrix.x4 per mt
            //   matrices: (rows jl*8, k-chunk 2ks+jh)
            const int kcA = 2*ks + jh;
            #pragma unroll
            for (int mt = 0; mt < 2; mt++) {
                int r_ = ar0 + mt*16;
                uint32_t addr = A_ + (uint32_t)(r_*32 + ((kcA ^ (r_ & 7)) << 2))*4u;
                ldmx4(af[mt][0], af[mt][1], af[mt][2], af[mt][3], addr);
            }
            // B frags: one ldmatrix.x4 per pair of nt
            //   matrices: (nt = 2p+jh, k-chunk 2ks+jl)
            const int kcB = 2*ks + jl;
            #pragma unroll
            for (int p = 0; p < 4; p++) {
                int r_ = brow[p];
                uint32_t addr = B_ + (uint32_t)(r_*32 + ((kcB ^ (r_ & 7)) << 2))*4u;
                ldmx4(bf[2*p][0], bf[2*p][1], bf[2*p+1][0], bf[2*p+1][1], addr);
            }
            #pragma unroll
            for (int mt = 0; mt < 2; mt++)
                #pragma unroll
                for (int nt = 0; nt < 8; nt++)
                    mma_tf32(c[mt][nt], af[mt], bf[nt]);
        }
    }
    asm volatile("cp.async.wait_group 0;");
    __syncthreads();

    // ---- stage C through smem so (a,g) pairs are visible to one thread ----
    float* Cs = sm;                       // [128][132]
    #pragma unroll
    for (int mt = 0; mt < 2; mt++)
        #pragma unroll
        for (int nt = 0; nt < 8; nt++) {
            int r = wm + mt*16 + g, cc = wn + nt*8 + 2*t;
            Cs[ r   *132 + cc    ] = c[mt][nt][0];
            Cs[ r   *132 + cc + 1] = c[mt][nt][1];
            Cs[(r+8)*132 + cc    ] = c[mt][nt][2];
            Cs[(r+8)*132 + cc + 1] = c[mt][nt][3];
        }
    __syncthreads();

    // ---- bias + GLU + residual, write final output ----
    #pragma unroll
    for (int i = 0; i < 32; i++) {
        int idx = i*256 + tid;            // 128*64 outputs
        int r = idx >> 6, j = idx & 63;
        int h = nT*64 + j;
        float a  = Cs[r*132 + j     ] + bias[h];
        float gg = Cs[r*132 + j + 64] + bias[h + 768];
        float sg = 1.0f / (1.0f + expf(-gg));
        size_t off = (size_t)(m0 + r)*HH + h;
        out[off] = a * sg + x[off];
    }
    #undef ISSUE_STAGE
}

// ---------------- launch ----------------
extern "C" void kernel_launch(void* const* d_in, const int* in_sizes, int n_in,
                              void* d_out, int out_size) {
    const float* x    = (const float*)d_in[0];   // (8, 8192, 768)
    const float* ker  = (const float*)d_in[1];   // (1, 768, 8192)
    const float* D    = (const float*)d_in[2];   // (1, 768)
    const float* W    = (const float*)d_in[3];   // (1536, 768)
    const float* bias = (const float*)d_in[4];   // (1536,)
    float* out = (float*)d_out;                  // (8, 8192, 768)

    k_taps<<<HH, 256>>>(ker);
    k_wprep<<<(NT*128*KK + 255)/256, 256>>>(W);
    k_v<<<(MM*(HH/4))/256, 256>>>(x, D);

    (void)cudaFuncSetAttribute(k_gemm, cudaFuncAttributeMaxDynamicSharedMemorySize,
                               SMEM_GEMM_BYTES);
    dim3 grid(NT, MM/128);
    k_gemm<<<grid, 256, SMEM_GEMM_BYTES>>>(x, bias, out);
}

// round 7
// speedup vs baseline: 2.3407x; 1.3430x over previous
#include <cuda_runtime.h>
#include <cuda_fp16.h>
#include <cstdint>
#include <math.h>

// Problem constants
#define BB   8
#define SS   8192
#define HH   768
#define MM   (BB*SS)      // 65536 GEMM rows
#define KK   768          // GEMM K
#define NT   12           // number of 64-wide a/g column tiles (768/64)
#define LAM  0.1f

#define BKT  64           // GEMM k-tile (fp16 elements; 128B per row)
#define KITR (KK/BKT)     // 12
#define STAGE_H (128*64)  // halves per smem stage per matrix (8192 = 16KB)
#define SMEM_GEMM_BYTES (2*3*STAGE_H*2)   // 98304 -> 96KB (2 CTAs/SM = 192KB of 228KB)

// ---------------- device scratch (allocation-free rule: __device__ globals) ----
__device__ __half g_v[(size_t)MM*HH];       // silu(x*D + conv) in fp16 (100MB)
__device__ __half g_w[NT*128*KK];           // W permuted into [nT][128 rows: 64 a | 64 g][K], fp16
__device__ float  g_tapv[HH*SS];            // compacted soft-thresholded kernel taps (value)
__device__ int    g_tapi[HH*SS];            // compacted taps (delay index)
__device__ int    g_nnz[HH];                // taps per channel

// ---------------- helpers ----------------
__device__ __forceinline__ void cp16(void* s, const void* g) {
    uint32_t sa = (uint32_t)__cvta_generic_to_shared(s);
    asm volatile("cp.async.cg.shared.global [%0], [%1], 16;" :: "r"(sa), "l"(g));
}
__device__ __forceinline__ void cp_commit() { asm volatile("cp.async.commit_group;"); }

__device__ __forceinline__ void ldmx4(uint32_t& r0, uint32_t& r1, uint32_t& r2, uint32_t& r3,
                                      uint32_t addr) {
    asm volatile("ldmatrix.sync.aligned.m8n8.x4.shared.b16 {%0,%1,%2,%3}, [%4];"
                 : "=r"(r0), "=r"(r1), "=r"(r2), "=r"(r3) : "r"(addr));
}

__device__ __forceinline__ void mma_f16(float c[4], const uint32_t a[4], const uint32_t b[2]) {
    asm("mma.sync.aligned.m16n8k16.row.col.f32.f16.f16.f32 "
        "{%0,%1,%2,%3}, {%4,%5,%6,%7}, {%8,%9}, {%0,%1,%2,%3};"
        : "+f"(c[0]), "+f"(c[1]), "+f"(c[2]), "+f"(c[3])
        : "r"(a[0]), "r"(a[1]), "r"(a[2]), "r"(a[3]), "r"(b[0]), "r"(b[1]));
}

// ---------------- kernel 1: soft-threshold + compact nonzero taps per channel ----
__global__ void k_taps(const float* __restrict__ ker) {
    __shared__ int cnt;
    const int h = blockIdx.x;
    if (threadIdx.x == 0) cnt = 0;
    __syncthreads();
    const float* kr = ker + (size_t)h*SS;
    for (int t = threadIdx.x; t < SS; t += blockDim.x) {
        float kv = kr[t];
        float av = fabsf(kv) - LAM;
        if (av > 0.0f) {
            int p = atomicAdd(&cnt, 1);
            g_tapv[(size_t)h*SS + p] = copysignf(av, kv);
            g_tapi[(size_t)h*SS + p] = t;
        }
    }
    __syncthreads();
    if (threadIdx.x == 0) g_nnz[h] = cnt;
}

// ---------------- kernel 2: permute W into a/g-paired tiles (fp16) ------------
__global__ void k_wprep(const float* __restrict__ W) {
    int idx = blockIdx.x * blockDim.x + threadIdx.x;
    if (idx >= NT*128*KK) return;
    int k  = idx % KK;
    int r  = (idx / KK) % 128;
    int nT = idx / (128*KK);
    int srcRow = (r < 64) ? (nT*64 + r) : (768 + nT*64 + (r - 64));
    g_w[idx] = __float2half_rn(W[(size_t)srcRow*KK + k]);
}

// ---------------- kernel 3: v = silu(x*D + sparse_conv) -> fp16 ---------------
__global__ void k_v(const float* __restrict__ x, const float* __restrict__ D) {
    int i4 = blockIdx.x * blockDim.x + threadIdx.x;   // float4 index over M*H/4
    int m  = i4 / (HH/4);
    int h0 = (i4 - m*(HH/4)) * 4;
    const float4 xv = *(const float4*)(x + (size_t)m*HH + h0);
    const float4 dv = *(const float4*)(D + h0);
    const int4  nn = *(const int4*)(g_nnz + h0);
    float y[4] = { xv.x*dv.x, xv.y*dv.y, xv.z*dv.z, xv.w*dv.w };
    if (nn.x | nn.y | nn.z | nn.w) {     // sparse causal conv (general correctness path)
        const int s = m & (SS-1);
        const int nnc[4] = { nn.x, nn.y, nn.z, nn.w };
        for (int c = 0; c < 4; c++) {
            const int h = h0 + c;
            for (int j = 0; j < nnc[c]; j++) {
                int t = g_tapi[(size_t)h*SS + j];
                if (t <= s) y[c] += g_tapv[(size_t)h*SS + j] * x[(size_t)(m - t)*HH + h];
            }
        }
    }
    float sv[4];
    #pragma unroll
    for (int c = 0; c < 4; c++) sv[c] = y[c] / (1.0f + expf(-y[c]));   // silu
    __half2 o0 = __floats2half2_rn(sv[0], sv[1]);
    __half2 o1 = __floats2half2_rn(sv[2], sv[3]);
    *(__half2*)(g_v + (size_t)m*HH + h0    ) = o0;
    *(__half2*)(g_v + (size_t)m*HH + h0 + 2) = o1;
}

// ---------------- kernel 4: fp16 GEMM + bias + GLU + residual -----------------
// C[128 x 128] = v_tile @ g_w_tile^T ; local cols [0,64)=a, [64,128)=g (same h)
// Stage: [128 rows][64 halves] = 128B/row; 16B-granule XOR swizzle.
__global__ void __launch_bounds__(256, 2)
k_gemm(const float* __restrict__ x, const float* __restrict__ bias,
       float* __restrict__ out) {
    extern __shared__ __align__(16) char smraw[];
    __half* As = (__half*)smraw;               // [3][128][64]
    __half* Bs = As + 3*STAGE_H;

    const int tid  = threadIdx.x;
    const int warp = tid >> 5, lane = tid & 31;
    const int g    = lane >> 2, t = lane & 3;
    const int wm   = (warp & 3) * 32;    // warp M offset (4 warps in M)
    const int wn   = (warp >> 2) * 64;   // warp N offset (2 warps in N)
    const int nT   = blockIdx.x;
    const int m0   = blockIdx.y * 128;

    const __half* gA = g_v + (size_t)m0*KK;
    const __half* gB = g_w + (size_t)nT*128*KK;

    const int lr = tid >> 3;             // load row 0..31 (x4 iters -> 128 rows)
    const int lcc = tid & 7;             // load chunk (16B = 8 halves)

    // ldmatrix lane decomposition: matrix j = lane>>3, row-in-matrix ri = lane&7
    const int jl = (lane >> 3) & 1;      // A: row-half   | B: k-chunk half
    const int jh = (lane >> 3) >> 1;     // A: k-chunk half | B: nt-in-pair
    const int ri = lane & 7;
    const int ar0 = wm + jl*8 + ri;      // A row for mt=0 (mt=1 adds 16)
    int brow[4];                          // B rows for x4 groups p=0..3 (nt = 2p+jh)
    #pragma unroll
    for (int p = 0; p < 4; p++) brow[p] = wn + (2*p + jh)*8 + ri;

    const uint32_t smA = (uint32_t)__cvta_generic_to_shared(As);
    const uint32_t smB = (uint32_t)__cvta_generic_to_shared(Bs);

    float c[2][8][4];
    #pragma unroll
    for (int i = 0; i < 2; i++)
        #pragma unroll
        for (int j = 0; j < 8; j++)
            #pragma unroll
            for (int q = 0; q < 4; q++) c[i][j][q] = 0.0f;

    // ---- async stage loader: elem (r, chunk c) at r*64 + ((c ^ (r&7))<<3) halves
    #define ISSUE_STAGE(stg, kt_)                                              \
    {                                                                          \
        const int k0_ = (kt_) * BKT;                                           \
        _Pragma("unroll")                                                      \
        for (int i_ = 0; i_ < 4; i_++) {                                       \
            int r_  = lr + i_*32;                                              \
            int sw_ = ((lcc ^ (r_ & 7)) << 3);                                 \
            cp16(As + (stg)*STAGE_H + r_*64 + sw_, gA + (size_t)r_*KK + k0_ + lcc*8); \
            cp16(Bs + (stg)*STAGE_H + r_*64 + sw_, gB + (size_t)r_*KK + k0_ + lcc*8); \
        }                                                                      \
    }

    ISSUE_STAGE(0, 0); cp_commit();
    ISSUE_STAGE(1, 1); cp_commit();

    for (int kt = 0; kt < KITR; kt++) {
        asm volatile("cp.async.wait_group 1;");
        __syncthreads();
        if (kt + 2 < KITR) { ISSUE_STAGE((kt+2)%3, kt+2); }
        cp_commit();

        const uint32_t A_ = smA + (uint32_t)((kt%3)*STAGE_H)*2u;
        const uint32_t B_ = smB + (uint32_t)((kt%3)*STAGE_H)*2u;

        #pragma unroll
        for (int ks = 0; ks < 4; ks++) {     // 4 x k16 per stage
            uint32_t af[2][4], bf[8][2];
            // A frags: one ldmatrix.x4 per mt; matrices (row-half jl, k-chunk 2ks+jh)
            const int kcA = 2*ks + jh;
            #pragma unroll
            for (int mt = 0; mt < 2; mt++) {
                int r_ = ar0 + mt*16;
                uint32_t addr = A_ + (uint32_t)(r_*128 + ((kcA ^ (r_ & 7)) << 4));
                ldmx4(af[mt][0], af[mt][1], af[mt][2], af[mt][3], addr);
            }
            // B frags: one ldmatrix.x4 per nt pair; matrices (nt 2p+jh, k-chunk 2ks+jl)
            const int kcB = 2*ks + jl;
            #pragma unroll
            for (int p = 0; p < 4; p++) {
                int r_ = brow[p];
                uint32_t addr = B_ + (uint32_t)(r_*128 + ((kcB ^ (r_ & 7)) << 4));
                ldmx4(bf[2*p][0], bf[2*p][1], bf[2*p+1][0], bf[2*p+1][1], addr);
            }
            #pragma unroll
            for (int mt = 0; mt < 2; mt++)
                #pragma unroll
                for (int nt = 0; nt < 8; nt++)
                    mma_f16(c[mt][nt], af[mt], bf[nt]);
        }
    }
    asm volatile("cp.async.wait_group 0;");
    __syncthreads();

    // ---- stage C through smem so (a,g) pairs are visible to one thread ----
    float* Cs = (float*)smraw;            // [128][132] = 67.6KB < 96KB
    #pragma unroll
    for (int mt = 0; mt < 2; mt++)
        #pragma unroll
        for (int nt = 0; nt < 8; nt++) {
            int r = wm + mt*16 + g, cc = wn + nt*8 + 2*t;
            Cs[ r   *132 + cc    ] = c[mt][nt][0];
            Cs[ r   *132 + cc + 1] = c[mt][nt][1];
            Cs[(r+8)*132 + cc    ] = c[mt][nt][2];
            Cs[(r+8)*132 + cc + 1] = c[mt][nt][3];
        }
    __syncthreads();

    // ---- bias + GLU + residual, write final output ----
    #pragma unroll
    for (int i = 0; i < 32; i++) {
        int idx = i*256 + tid;            // 128*64 outputs
        int r = idx >> 6, j = idx & 63;
        int h = nT*64 + j;
        float a  = Cs[r*132 + j     ] + bias[h];
        float gg = Cs[r*132 + j + 64] + bias[h + 768];
        float sg = 1.0f / (1.0f + expf(-gg));
        size_t off = (size_t)(m0 + r)*HH + h;
        out[off] = a * sg + x[off];
    }
    #undef ISSUE_STAGE
}

// ---------------- launch ----------------
extern "C" void kernel_launch(void* const* d_in, const int* in_sizes, int n_in,
                              void* d_out, int out_size) {
    const float* x    = (const float*)d_in[0];   // (8, 8192, 768)
    const float* ker  = (const float*)d_in[1];   // (1, 768, 8192)
    const float* D    = (const float*)d_in[2];   // (1, 768)
    const float* W    = (const float*)d_in[3];   // (1536, 768)
    const float* bias = (const float*)d_in[4];   // (1536,)
    float* out = (float*)d_out;                  // (8, 8192, 768)

    k_taps<<<HH, 256>>>(ker);
    k_wprep<<<(NT*128*KK + 255)/256, 256>>>(W);
    k_v<<<(MM*(HH/4))/256, 256>>>(x, D);

    (void)cudaFuncSetAttribute(k_gemm, cudaFuncAttributeMaxDynamicSharedMemorySize,
                               SMEM_GEMM_BYTES);
    dim3 grid(NT, MM/128);
    k_gemm<<<grid, 256, SMEM_GEMM_BYTES>>>(x, bias, out);
}

// round 8
// speedup vs baseline: 2.6986x; 1.1529x over previous
#include <cuda_runtime.h>
#include <cuda_fp16.h>
#include <cstdint>
#include <math.h>

// Problem constants
#define BB   8
#define SS   8192
#define HH   768
#define MM   (BB*SS)      // 65536 GEMM rows
#define KK   768          // GEMM K
#define NT   24           // number of 32-wide a/g column tiles (768/32)
#define LAM  0.1f

#define BKT  64           // GEMM k-tile (fp16 elements; 128B per row)
#define KITR (KK/BKT)     // 12
#define BNR  64           // B rows per tile (32 a + 32 g)
#define A_STG_H (128*64)  // 8192 halves
#define B_STG_H (BNR*64)  // 4096 halves
#define STG_H   (A_STG_H + B_STG_H)       // 12288 halves = 24KB
#define SMEM_GEMM_BYTES (3*STG_H*2)       // 73728 -> 72KB (3 CTAs/SM = 216KB)

// ---------------- device scratch ----------------
__device__ __half g_v[(size_t)MM*HH];       // silu(x*D + conv) in fp16 (100MB)
__device__ __half g_w[NT*BNR*KK];           // W permuted: [nT][64 rows: 32 a | 32 g][K]
__device__ float  g_tapv[HH*SS];
__device__ int    g_tapi[HH*SS];
__device__ int    g_nnz[HH];

// ---------------- helpers ----------------
__device__ __forceinline__ void cp16(void* s, const void* g) {
    uint32_t sa = (uint32_t)__cvta_generic_to_shared(s);
    asm volatile("cp.async.cg.shared.global [%0], [%1], 16;" :: "r"(sa), "l"(g));
}
__device__ __forceinline__ void cp_commit() { asm volatile("cp.async.commit_group;"); }

__device__ __forceinline__ void ldmx4(uint32_t& r0, uint32_t& r1, uint32_t& r2, uint32_t& r3,
                                      uint32_t addr) {
    asm volatile("ldmatrix.sync.aligned.m8n8.x4.shared.b16 {%0,%1,%2,%3}, [%4];"
                 : "=r"(r0), "=r"(r1), "=r"(r2), "=r"(r3) : "r"(addr));
}

__device__ __forceinline__ void mma_f16(float c[4], const uint32_t a[4], const uint32_t b[2]) {
    asm("mma.sync.aligned.m16n8k16.row.col.f32.f16.f16.f32 "
        "{%0,%1,%2,%3}, {%4,%5,%6,%7}, {%8,%9}, {%0,%1,%2,%3};"
        : "+f"(c[0]), "+f"(c[1]), "+f"(c[2]), "+f"(c[3])
        : "r"(a[0]), "r"(a[1]), "r"(a[2]), "r"(a[3]), "r"(b[0]), "r"(b[1]));
}

// ---------------- kernel 1: soft-threshold + compact taps ----------------
__global__ void k_taps(const float* __restrict__ ker) {
    __shared__ int cnt;
    const int h = blockIdx.x;
    if (threadIdx.x == 0) cnt = 0;
    __syncthreads();
    const float* kr = ker + (size_t)h*SS;
    for (int t = threadIdx.x; t < SS; t += blockDim.x) {
        float kv = kr[t];
        float av = fabsf(kv) - LAM;
        if (av > 0.0f) {
            int p = atomicAdd(&cnt, 1);
            g_tapv[(size_t)h*SS + p] = copysignf(av, kv);
            g_tapi[(size_t)h*SS + p] = t;
        }
    }
    __syncthreads();
    if (threadIdx.x == 0) g_nnz[h] = cnt;
}

// ---------------- kernel 2: permute W into a/g-paired tiles (fp16) ------------
// g_w[nT][r][k]: r<32 -> W[nT*32 + r] ('a'); r>=32 -> W[768 + nT*32 + (r-32)] ('g')
__global__ void k_wprep(const float* __restrict__ W) {
    int idx = blockIdx.x * blockDim.x + threadIdx.x;
    if (idx >= NT*BNR*KK) return;
    int k  = idx % KK;
    int r  = (idx / KK) % BNR;
    int nT = idx / (BNR*KK);
    int srcRow = (r < 32) ? (nT*32 + r) : (768 + nT*32 + (r - 32));
    g_w[idx] = __float2half_rn(W[(size_t)srcRow*KK + k]);
}

// ---------------- kernel 3: v = silu(x*D + sparse_conv) -> fp16 ---------------
__global__ void k_v(const float* __restrict__ x, const float* __restrict__ D) {
    int i4 = blockIdx.x * blockDim.x + threadIdx.x;
    int m  = i4 / (HH/4);
    int h0 = (i4 - m*(HH/4)) * 4;
    const float4 xv = *(const float4*)(x + (size_t)m*HH + h0);
    const float4 dv = *(const float4*)(D + h0);
    const int4  nn = *(const int4*)(g_nnz + h0);
    float y[4] = { xv.x*dv.x, xv.y*dv.y, xv.z*dv.z, xv.w*dv.w };
    if (nn.x | nn.y | nn.z | nn.w) {
        const int s = m & (SS-1);
        const int nnc[4] = { nn.x, nn.y, nn.z, nn.w };
        for (int c = 0; c < 4; c++) {
            const int h = h0 + c;
            for (int j = 0; j < nnc[c]; j++) {
                int t = g_tapi[(size_t)h*SS + j];
                if (t <= s) y[c] += g_tapv[(size_t)h*SS + j] * x[(size_t)(m - t)*HH + h];
            }
        }
    }
    float sv[4];
    #pragma unroll
    for (int c = 0; c < 4; c++) sv[c] = y[c] / (1.0f + expf(-y[c]));
    *(__half2*)(g_v + (size_t)m*HH + h0    ) = __floats2half2_rn(sv[0], sv[1]);
    *(__half2*)(g_v + (size_t)m*HH + h0 + 2) = __floats2half2_rn(sv[2], sv[3]);
}

// ---------------- kernel 4: fp16 GEMM + bias + GLU + residual -----------------
// CTA tile: C[128 x 64]; local cols [0,32)=a, [32,64)=g (same h).
// 8 warps: 4 in M (32 rows each) x 2 in N (32 cols each). 3 CTAs/SM.
__global__ void __launch_bounds__(256, 3)
k_gemm(const float* __restrict__ x, const float* __restrict__ bias,
       float* __restrict__ out) {
    extern __shared__ __align__(16) char smraw[];
    __half* St = (__half*)smraw;               // 3 stages of [A 128x64 | B 64x64]

    const int tid  = threadIdx.x;
    const int warp = tid >> 5, lane = tid & 31;
    const int g    = lane >> 2, t = lane & 3;
    const int wm   = (warp & 3) * 32;    // warp M offset (4 warps in M)
    const int wn   = (warp >> 2) * 32;   // warp N offset (2 warps in N)
    const int nT   = blockIdx.x;
    const int m0   = blockIdx.y * 128;

    const __half* gA = g_v + (size_t)m0*KK;
    const __half* gB = g_w + (size_t)nT*BNR*KK;

    // ldmatrix lane decomposition: matrix j = lane>>3, row-in-matrix ri = lane&7
    const int jl = (lane >> 3) & 1;
    const int jh = (lane >> 3) >> 1;
    const int ri = lane & 7;
    const int ar0 = wm + jl*8 + ri;      // A row for mt=0 (mt=1 adds 16)
    int brow[2];                          // B rows for x4 groups p=0..1 (nt = 2p+jh)
    #pragma unroll
    for (int p = 0; p < 2; p++) brow[p] = wn + (2*p + jh)*8 + ri;

    const uint32_t smS = (uint32_t)__cvta_generic_to_shared(St);

    float c[2][4][4];
    #pragma unroll
    for (int i = 0; i < 2; i++)
        #pragma unroll
        for (int j = 0; j < 4; j++)
            #pragma unroll
            for (int q = 0; q < 4; q++) c[i][j][q] = 0.0f;

    // ---- async stage loader: 192 rows x 8 chunks(16B) = 1536 loads / 256 thr = 6 ea
    // elem (row r, chunk cc) at stage + r*64 + ((cc ^ (r&7))<<3) halves
    #define ISSUE_STAGE(stg, kt_)                                              \
    {                                                                          \
        const int k0_ = (kt_) * BKT;                                           \
        _Pragma("unroll")                                                      \
        for (int i_ = 0; i_ < 6; i_++) {                                       \
            int li_ = tid + i_*256;                                            \
            int r_  = li_ >> 3, cc_ = li_ & 7;                                 \
            const __half* src_ = (r_ < 128)                                    \
                ? gA + (size_t)r_*KK + k0_ + cc_*8                             \
                : gB + (size_t)(r_-128)*KK + k0_ + cc_*8;                      \
            cp16(St + (stg)*STG_H + r_*64 + ((cc_ ^ (r_ & 7)) << 3), src_);    \
        }                                                                      \
    }

    ISSUE_STAGE(0, 0); cp_commit();
    ISSUE_STAGE(1, 1); cp_commit();

    for (int kt = 0; kt < KITR; kt++) {
        asm volatile("cp.async.wait_group 1;");
        __syncthreads();
        if (kt + 2 < KITR) { ISSUE_STAGE((kt+2)%3, kt+2); }
        cp_commit();

        const uint32_t A_ = smS + (uint32_t)((kt%3)*STG_H)*2u;
        const uint32_t B_ = A_ + (uint32_t)A_STG_H*2u;

        #pragma unroll
        for (int ks = 0; ks < 4; ks++) {     // 4 x k16 per stage
            uint32_t af[2][4], bf[4][2];
            const int kcA = 2*ks + jh;
            #pragma unroll
            for (int mt = 0; mt < 2; mt++) {
                int r_ = ar0 + mt*16;
                uint32_t addr = A_ + (uint32_t)(r_*128 + ((kcA ^ (r_ & 7)) << 4));
                ldmx4(af[mt][0], af[mt][1], af[mt][2], af[mt][3], addr);
            }
            const int kcB = 2*ks + jl;
            #pragma unroll
            for (int p = 0; p < 2; p++) {
                int r_ = brow[p];
                uint32_t addr = B_ + (uint32_t)(r_*128 + ((kcB ^ (r_ & 7)) << 4));
                ldmx4(bf[2*p][0], bf[2*p][1], bf[2*p+1][0], bf[2*p+1][1], addr);
            }
            #pragma unroll
            for (int mt = 0; mt < 2; mt++)
                #pragma unroll
                for (int nt = 0; nt < 4; nt++)
                    mma_f16(c[mt][nt], af[mt], bf[nt]);
        }
    }
    asm volatile("cp.async.wait_group 0;");
    __syncthreads();

    // ---- stage C through smem so (a,g) pairs are visible to one thread ----
    float* Cs = (float*)smraw;            // [128][68] = 34.8KB < 72KB
    #pragma unroll
    for (int mt = 0; mt < 2; mt++)
        #pragma unroll
        for (int nt = 0; nt < 4; nt++) {
            int r = wm + mt*16 + g, cc = wn + nt*8 + 2*t;
            Cs[ r   *68 + cc    ] = c[mt][nt][0];
            Cs[ r   *68 + cc + 1] = c[mt][nt][1];
            Cs[(r+8)*68 + cc    ] = c[mt][nt][2];
            Cs[(r+8)*68 + cc + 1] = c[mt][nt][3];
        }
    __syncthreads();

    // ---- bias + GLU + residual, write final output ----
    #pragma unroll
    for (int i = 0; i < 16; i++) {
        int idx = i*256 + tid;            // 128*32 outputs
        int r = idx >> 5, j = idx & 31;
        int h = nT*32 + j;
        float a  = Cs[r*68 + j     ] + bias[h];
        float gg = Cs[r*68 + j + 32] + bias[h + 768];
        float sg = 1.0f / (1.0f + expf(-gg));
        size_t off = (size_t)(m0 + r)*HH + h;
        out[off] = a * sg + x[off];
    }
    #undef ISSUE_STAGE
}

// ---------------- launch ----------------
extern "C" void kernel_launch(void* const* d_in, const int* in_sizes, int n_in,
                              void* d_out, int out_size) {
    const float* x    = (const float*)d_in[0];   // (8, 8192, 768)
    const float* ker  = (const float*)d_in[1];   // (1, 768, 8192)
    const float* D    = (const float*)d_in[2];   // (1, 768)
    const float* W    = (const float*)d_in[3];   // (1536, 768)
    const float* bias = (const float*)d_in[4];   // (1536,)
    float* out = (float*)d_out;                  // (8, 8192, 768)

    k_taps<<<HH, 256>>>(ker);
    k_wprep<<<(NT*BNR*KK + 255)/256, 256>>>(W);
    k_v<<<(MM*(HH/4))/256, 256>>>(x, D);

    (void)cudaFuncSetAttribute(k_gemm, cudaFuncAttributeMaxDynamicSharedMemorySize,
                               SMEM_GEMM_BYTES);
    dim3 grid(NT, MM/128);
    k_gemm<<<grid, 256, SMEM_GEMM_BYTES>>>(x, bias, out);
}